// round 3
// baseline (speedup 1.0000x reference)
#include <cuda_runtime.h>
#include <cstdint>

#define N_NODES 100000
#define N_EDGES 800000
#define C 64

// Scratch (device globals — no allocation allowed in kernel_launch)
__device__ float g_h2[(size_t)N_NODES * C];   // (x@W) * dinv[row]
__device__ float g_acc[(size_t)N_NODES * C];  // scatter accumulator
__device__ float g_deg[N_NODES];              // degree (incl. self-loop)

// ---------------------------------------------------------------------------
// K0: zero accumulator, deg = 1 (self loop)
// ---------------------------------------------------------------------------
__global__ void k_init() {
    int i = blockIdx.x * blockDim.x + threadIdx.x;
    const int total4 = N_NODES * C / 4;
    if (i < total4) ((float4*)g_acc)[i] = make_float4(0.f, 0.f, 0.f, 0.f);
    if (i < N_NODES) g_deg[i] = 1.0f;
}

// ---------------------------------------------------------------------------
// K1: degree count over dst (edge_index arrives as int32 from the harness)
// ---------------------------------------------------------------------------
__global__ void k_count(const int* __restrict__ ei) {
    int e = blockIdx.x * blockDim.x + threadIdx.x;
    if (e < N_EDGES) {
        int dst = ei[N_EDGES + e];
        atomicAdd(&g_deg[dst], 1.0f);
    }
}

// ---------------------------------------------------------------------------
// K2: h2 = (x @ W) * rsqrt(deg)
// 128 threads = 8 rows x 16 threads, each thread computes 4 adjacent columns.
// Inner loop: 1 broadcast LDS + 1 LDS.128 per 4 FMAs.
// ---------------------------------------------------------------------------
__global__ __launch_bounds__(128) void k_gemm1(const float* __restrict__ x,
                                               const float* __restrict__ W) {
    __shared__ float Ws[64 * 64];
    __shared__ float xs[8][65];  // pad to avoid bank conflict on xs[r][k]

    int tid = threadIdx.x;
    // Load W (4096 floats) — 8 float4 per thread
#pragma unroll
    for (int i = 0; i < 8; i++)
        ((float4*)Ws)[tid + 128 * i] = ((const float4*)W)[tid + 128 * i];

    int r = tid >> 4;      // local row 0..7
    int t = tid & 15;      // col group 0..15
    long long row = (long long)blockIdx.x * 8 + r;

    float4 xv4 = make_float4(0.f, 0.f, 0.f, 0.f);
    if (row < N_NODES) xv4 = *(const float4*)&x[row * 64 + t * 4];
    xs[r][t * 4 + 0] = xv4.x;
    xs[r][t * 4 + 1] = xv4.y;
    xs[r][t * 4 + 2] = xv4.z;
    xs[r][t * 4 + 3] = xv4.w;
    __syncthreads();

    float a0 = 0.f, a1 = 0.f, a2 = 0.f, a3 = 0.f;
#pragma unroll
    for (int k = 0; k < 64; k++) {
        float xv = xs[r][k];
        float4 w = *(float4*)&Ws[k * 64 + t * 4];
        a0 += xv * w.x;
        a1 += xv * w.y;
        a2 += xv * w.z;
        a3 += xv * w.w;
    }

    if (row < N_NODES) {
        float dinv = rsqrtf(g_deg[row]);
        float4 o = make_float4(a0 * dinv, a1 * dinv, a2 * dinv, a3 * dinv);
        *(float4*)&g_h2[row * 64 + t * 4] = o;
    }
}

// ---------------------------------------------------------------------------
// K3: edge scatter — acc[dst] += h2[src]
// 16 lanes per edge: one LDG.128 gather + one red.global.add.v4.f32 per lane.
// ---------------------------------------------------------------------------
__global__ __launch_bounds__(256) void k_scatter(const int* __restrict__ ei) {
    long long tid = (long long)blockIdx.x * blockDim.x + threadIdx.x;
    int e = (int)(tid >> 4);
    int j = (int)(tid & 15);
    if (e >= N_EDGES) return;
    int src = ei[e];
    int dst = ei[N_EDGES + e];
    float4 v = *(const float4*)&g_h2[(long long)src * 64 + j * 4];
    float* p = &g_acc[(long long)dst * 64 + j * 4];
    asm volatile("red.global.add.v4.f32 [%0], {%1, %2, %3, %4};"
                 :: "l"(p), "f"(v.x), "f"(v.y), "f"(v.z), "f"(v.w)
                 : "memory");
}

// ---------------------------------------------------------------------------
// K4: fused epilogue — gcn bias, LayerNorm, ReLU, gate by x, GEMM2 + fcb
// 256 threads = 8 rows x 32 lanes; lane handles cols (l, l+32) for the row
// phase and cols (2l, 2l+1) for the output GEMM.
// ---------------------------------------------------------------------------
__global__ __launch_bounds__(256) void k_epi(const float* __restrict__ x,
                                             const float* __restrict__ b,
                                             const float* __restrict__ gamma,
                                             const float* __restrict__ beta,
                                             const float* __restrict__ fcW,
                                             const float* __restrict__ fcb,
                                             float* __restrict__ out) {
    __shared__ float Ws[64 * 64];
    __shared__ float rs[8][64];
    __shared__ float sb[64], sg[64], sbe[64], sfcb[64];

    int tid = threadIdx.x;
#pragma unroll
    for (int i = 0; i < 4; i++)
        ((float4*)Ws)[tid + 256 * i] = ((const float4*)fcW)[tid + 256 * i];
    if (tid < 64) {
        sb[tid] = b[tid];
        sg[tid] = gamma[tid];
        sbe[tid] = beta[tid];
        sfcb[tid] = fcb[tid];
    }
    __syncthreads();

    int w = tid >> 5;  // local row / warp
    int l = tid & 31;
    long long row = (long long)blockIdx.x * 8 + w;

    if (row < N_NODES) {
        float dinv = rsqrtf(g_deg[row]);
        long long base = row * 64;
        int c0 = l, c1 = l + 32;
        float v0 = (g_acc[base + c0] + g_h2[base + c0]) * dinv + sb[c0];
        float v1 = (g_acc[base + c1] + g_h2[base + c1]) * dinv + sb[c1];

        float s = v0 + v1;
#pragma unroll
        for (int o = 16; o; o >>= 1) s += __shfl_xor_sync(0xFFFFFFFFu, s, o);
        float mu = s * (1.0f / 64.0f);

        float d0 = v0 - mu, d1 = v1 - mu;
        float q = d0 * d0 + d1 * d1;
#pragma unroll
        for (int o = 16; o; o >>= 1) q += __shfl_xor_sync(0xFFFFFFFFu, q, o);
        float inv = rsqrtf(q * (1.0f / 64.0f) + 1e-5f);

        float r0 = d0 * inv * sg[c0] + sbe[c0];
        float r1 = d1 * inv * sg[c1] + sbe[c1];
        r0 = fmaxf(r0, 0.f) * x[base + c0];
        r1 = fmaxf(r1, 0.f) * x[base + c1];
        rs[w][c0] = r0;
        rs[w][c1] = r1;
    }
    __syncwarp();

    if (row < N_NODES) {
        float a0 = 0.f, a1 = 0.f;
#pragma unroll
        for (int k = 0; k < 64; k++) {
            float rv = rs[w][k];
            float2 wv = *(float2*)&Ws[k * 64 + l * 2];
            a0 += rv * wv.x;
            a1 += rv * wv.y;
        }
        float2 o;
        o.x = a0 + sfcb[l * 2];
        o.y = a1 + sfcb[l * 2 + 1];
        *(float2*)&out[row * 64 + l * 2] = o;
    }
}

// ---------------------------------------------------------------------------
extern "C" void kernel_launch(void* const* d_in, const int* in_sizes, int n_in,
                              void* d_out, int out_size) {
    const float* x     = (const float*)d_in[0];
    const int*   ei    = (const int*)d_in[1];   // int32 per harness metadata
    const float* W     = (const float*)d_in[2];
    const float* b     = (const float*)d_in[3];
    const float* gamma = (const float*)d_in[4];
    const float* beta  = (const float*)d_in[5];
    const float* fcW   = (const float*)d_in[6];
    const float* fcb   = (const float*)d_in[7];
    float* out = (float*)d_out;

    (void)in_sizes; (void)n_in; (void)out_size;

    // K0: init (covers max(N*C/4, N_NODES) threads)
    {
        int total = N_NODES * C / 4;  // 1.6M > N_NODES
        int blocks = (total + 255) / 256;
        k_init<<<blocks, 256>>>();
    }
    // K1: degree count
    k_count<<<(N_EDGES + 255) / 256, 256>>>(ei);
    // K2: h2 = (x@W) * dinv
    k_gemm1<<<(N_NODES + 7) / 8, 128>>>(x, W);
    // K3: edge scatter
    {
        long long threads = (long long)N_EDGES * 16;
        int blocks = (int)((threads + 255) / 256);
        k_scatter<<<blocks, 256>>>(ei);
    }
    // K4: fused epilogue
    k_epi<<<(N_NODES + 7) / 8, 256>>>(x, b, gamma, beta, fcW, fcb, out);
}

// round 4
// speedup vs baseline: 1.1276x; 1.1276x over previous
#include <cuda_runtime.h>
#include <cstdint>

#define N_NODES 100000
#define N_EDGES 800000
#define C 64

#define GEMM1_ROWS 16
#define GEMM1_TILES ((N_NODES + GEMM1_ROWS - 1) / GEMM1_ROWS)   // 6250
#define EPI_ROWS 8
#define EPI_TILES ((N_NODES + EPI_ROWS - 1) / EPI_ROWS)         // 12500

// Scratch (device globals — no allocation allowed in kernel_launch)
__device__ float g_h2[(size_t)N_NODES * C];   // (x@W) * dinv[row]
__device__ float g_acc[(size_t)N_NODES * C];  // accumulator, pre-seeded with h2 (self-loop)
__device__ float g_deg[N_NODES];              // degree (incl. self-loop)

// ---------------------------------------------------------------------------
// K0: deg = 1 (self loop). acc is NOT zeroed — gemm1 seeds it with h2.
// ---------------------------------------------------------------------------
__global__ void k_init() {
    int i = blockIdx.x * blockDim.x + threadIdx.x;
    if (i < N_NODES) g_deg[i] = 1.0f;
}

// ---------------------------------------------------------------------------
// K1: degree count over dst (edge_index arrives as int32 from the harness)
// ---------------------------------------------------------------------------
__global__ void k_count(const int* __restrict__ ei) {
    int e = blockIdx.x * blockDim.x + threadIdx.x;
    if (e < N_EDGES) {
        int dst = ei[N_EDGES + e];
        atomicAdd(&g_deg[dst], 1.0f);
    }
}

// ---------------------------------------------------------------------------
// K2: h2 = (x @ W) * rsqrt(deg); also seeds acc = h2 (self-loop term).
// Grid-stride persistent blocks: W staged in smem ONCE per block.
// 256 threads = 16 rows x 16 lanes; each lane computes 4 adjacent columns.
// ---------------------------------------------------------------------------
__global__ __launch_bounds__(256) void k_gemm1(const float* __restrict__ x,
                                               const float* __restrict__ W) {
    __shared__ float Ws[64 * 64];
    __shared__ float xs[GEMM1_ROWS][65];  // pad to avoid bank conflicts

    int tid = threadIdx.x;
#pragma unroll
    for (int i = 0; i < 4; i++)
        ((float4*)Ws)[tid + 256 * i] = ((const float4*)W)[tid + 256 * i];
    __syncthreads();

    int r = tid >> 4;   // local row 0..15
    int t = tid & 15;   // col group 0..15

    for (int tile = blockIdx.x; tile < GEMM1_TILES; tile += gridDim.x) {
        long long row = (long long)tile * GEMM1_ROWS + r;

        float4 xv4 = make_float4(0.f, 0.f, 0.f, 0.f);
        if (row < N_NODES) xv4 = *(const float4*)&x[row * 64 + t * 4];
        xs[r][t * 4 + 0] = xv4.x;
        xs[r][t * 4 + 1] = xv4.y;
        xs[r][t * 4 + 2] = xv4.z;
        xs[r][t * 4 + 3] = xv4.w;
        __syncthreads();

        float a0 = 0.f, a1 = 0.f, a2 = 0.f, a3 = 0.f;
#pragma unroll
        for (int k = 0; k < 64; k++) {
            float xv = xs[r][k];
            float4 w = *(float4*)&Ws[k * 64 + t * 4];
            a0 += xv * w.x;
            a1 += xv * w.y;
            a2 += xv * w.z;
            a3 += xv * w.w;
        }

        if (row < N_NODES) {
            float dinv = rsqrtf(g_deg[row]);
            float4 o = make_float4(a0 * dinv, a1 * dinv, a2 * dinv, a3 * dinv);
            *(float4*)&g_h2[row * 64 + t * 4] = o;
            *(float4*)&g_acc[row * 64 + t * 4] = o;  // self-loop seed
        }
        __syncthreads();  // protect xs before next tile overwrites it
    }
}

// ---------------------------------------------------------------------------
// K3: edge scatter — acc[dst] += h2[src]
// 16 lanes per edge: one LDG.128 gather + one red.global.add.v4.f32 per lane.
// ---------------------------------------------------------------------------
__global__ __launch_bounds__(256) void k_scatter(const int* __restrict__ ei) {
    long long tid = (long long)blockIdx.x * blockDim.x + threadIdx.x;
    int e = (int)(tid >> 4);
    int j = (int)(tid & 15);
    if (e >= N_EDGES) return;
    int src = ei[e];
    int dst = ei[N_EDGES + e];
    float4 v = *(const float4*)&g_h2[(long long)src * 64 + j * 4];
    float* p = &g_acc[(long long)dst * 64 + j * 4];
    asm volatile("red.global.add.v4.f32 [%0], {%1, %2, %3, %4};"
                 :: "l"(p), "f"(v.x), "f"(v.y), "f"(v.z), "f"(v.w)
                 : "memory");
}

// ---------------------------------------------------------------------------
// K4: fused epilogue — gcn = acc*dinv + b, LayerNorm, ReLU, gate by x,
// GEMM2 + fcb. Grid-stride persistent blocks: fcW staged in smem once.
// 256 threads = 8 warps, one warp per row; lane handles cols (l, l+32)
// for the row phase and cols (2l, 2l+1) for the output GEMM.
// ---------------------------------------------------------------------------
__global__ __launch_bounds__(256) void k_epi(const float* __restrict__ x,
                                             const float* __restrict__ b,
                                             const float* __restrict__ gamma,
                                             const float* __restrict__ beta,
                                             const float* __restrict__ fcW,
                                             const float* __restrict__ fcb,
                                             float* __restrict__ out) {
    __shared__ float Ws[64 * 64];
    __shared__ float rs[8][64];
    __shared__ float sb[64], sg[64], sbe[64], sfcb[64];

    int tid = threadIdx.x;
#pragma unroll
    for (int i = 0; i < 4; i++)
        ((float4*)Ws)[tid + 256 * i] = ((const float4*)fcW)[tid + 256 * i];
    if (tid < 64) {
        sb[tid] = b[tid];
        sg[tid] = gamma[tid];
        sbe[tid] = beta[tid];
        sfcb[tid] = fcb[tid];
    }
    __syncthreads();

    int w = tid >> 5;  // warp id = local row
    int l = tid & 31;

    for (int tile = blockIdx.x; tile < EPI_TILES; tile += gridDim.x) {
        long long row = (long long)tile * EPI_ROWS + w;
        if (row < N_NODES) {
            float dinv = rsqrtf(g_deg[row]);
            long long base = row * 64;
            int c0 = l, c1 = l + 32;
            float v0 = g_acc[base + c0] * dinv + sb[c0];
            float v1 = g_acc[base + c1] * dinv + sb[c1];

            float s = v0 + v1;
#pragma unroll
            for (int o = 16; o; o >>= 1) s += __shfl_xor_sync(0xFFFFFFFFu, s, o);
            float mu = s * (1.0f / 64.0f);

            float d0 = v0 - mu, d1 = v1 - mu;
            float q = d0 * d0 + d1 * d1;
#pragma unroll
            for (int o = 16; o; o >>= 1) q += __shfl_xor_sync(0xFFFFFFFFu, q, o);
            float inv = rsqrtf(q * (1.0f / 64.0f) + 1e-5f);

            float r0 = d0 * inv * sg[c0] + sbe[c0];
            float r1 = d1 * inv * sg[c1] + sbe[c1];
            r0 = fmaxf(r0, 0.f) * x[base + c0];
            r1 = fmaxf(r1, 0.f) * x[base + c1];
            rs[w][c0] = r0;
            rs[w][c1] = r1;
            __syncwarp();

            float a0 = 0.f, a1 = 0.f;
#pragma unroll
            for (int k = 0; k < 64; k++) {
                float rv = rs[w][k];
                float2 wv = *(float2*)&Ws[k * 64 + l * 2];
                a0 += rv * wv.x;
                a1 += rv * wv.y;
            }
            float2 o;
            o.x = a0 + sfcb[l * 2];
            o.y = a1 + sfcb[l * 2 + 1];
            *(float2*)&out[row * 64 + l * 2] = o;
            __syncwarp();  // rs[w] reuse next tile
        }
    }
}

// ---------------------------------------------------------------------------
extern "C" void kernel_launch(void* const* d_in, const int* in_sizes, int n_in,
                              void* d_out, int out_size) {
    const float* x     = (const float*)d_in[0];
    const int*   ei    = (const int*)d_in[1];   // int32 per harness metadata
    const float* W     = (const float*)d_in[2];
    const float* b     = (const float*)d_in[3];
    const float* gamma = (const float*)d_in[4];
    const float* beta  = (const float*)d_in[5];
    const float* fcW   = (const float*)d_in[6];
    const float* fcb   = (const float*)d_in[7];
    float* out = (float*)d_out;

    (void)in_sizes; (void)n_in; (void)out_size;

    // K0: deg = 1
    k_init<<<(N_NODES + 255) / 256, 256>>>();
    // K1: degree count
    k_count<<<(N_EDGES + 255) / 256, 256>>>(ei);
    // K2: h2 = (x@W)*dinv, acc seeded with h2
    k_gemm1<<<592, 256>>>(x, W);
    // K3: edge scatter
    {
        long long threads = (long long)N_EDGES * 16;
        int blocks = (int)((threads + 255) / 256);
        k_scatter<<<blocks, 256>>>(ei);
    }
    // K4: fused epilogue
    k_epi<<<1184, 256>>>(x, b, gamma, beta, fcW, fcb, out);
}

// round 5
// speedup vs baseline: 1.5549x; 1.3789x over previous
#include <cuda_runtime.h>
#include <cstdint>

#define N_NODES 100000
#define N_EDGES 800000
#define C 64

#define TILE_ROWS 64
#define N_TILES ((N_NODES + TILE_ROWS - 1) / TILE_ROWS)  // 1563

// Scratch (device globals — no allocation allowed in kernel_launch)
__device__ float g_h2[(size_t)N_NODES * C];   // (x@W) * dinv[row]
__device__ float g_acc[(size_t)N_NODES * C];  // accumulator, pre-seeded with h2 (self-loop)
__device__ float g_deg[N_NODES];              // degree (incl. self-loop)

// ---- Blackwell packed f32x2 helpers (FFMA2: 2 fp32 FMAs per issue) --------
__device__ __forceinline__ unsigned long long pack2(float lo, float hi) {
    unsigned long long r;
    asm("mov.b64 %0, {%1, %2};" : "=l"(r) : "f"(lo), "f"(hi));
    return r;
}
__device__ __forceinline__ void unpack2(unsigned long long v, float& lo, float& hi) {
    asm("mov.b64 {%0, %1}, %2;" : "=f"(lo), "=f"(hi) : "l"(v));
}
__device__ __forceinline__ unsigned long long ffma2(unsigned long long a,
                                                    unsigned long long b,
                                                    unsigned long long c) {
    unsigned long long d;
    asm("fma.rn.f32x2 %0, %1, %2, %3;" : "=l"(d) : "l"(a), "l"(b), "l"(c));
    return d;
}

// ---------------------------------------------------------------------------
// K0: deg = 1 (self loop). acc is NOT zeroed — gemm1 seeds it with h2.
// ---------------------------------------------------------------------------
__global__ void k_init() {
    int i = blockIdx.x * blockDim.x + threadIdx.x;
    if (i < N_NODES) g_deg[i] = 1.0f;
}

// ---------------------------------------------------------------------------
// K1: degree count over dst (edge_index arrives as int32 from the harness)
// ---------------------------------------------------------------------------
__global__ void k_count(const int* __restrict__ ei) {
    int e = blockIdx.x * blockDim.x + threadIdx.x;
    if (e < N_EDGES) {
        int dst = ei[N_EDGES + e];
        atomicAdd(&g_deg[dst], 1.0f);
    }
}

// ---------------------------------------------------------------------------
// K2: h2 = (x @ W) * rsqrt(deg); also seeds acc = h2 (self-loop term).
// Persistent blocks, W staged once. Register-tiled: 256 threads as 16x16,
// each thread computes a 4-row x 4-col micro-tile with f32x2 FMAs.
// Per 4 k-steps per thread: 8 LDS.128 feeding 32 FFMA2 -> FMA-bound.
// ---------------------------------------------------------------------------
__global__ __launch_bounds__(256) void k_gemm1(const float* __restrict__ x,
                                               const float* __restrict__ W) {
    __shared__ float Ws[64 * 64];    // k-major: Ws[k*64 + col]
    __shared__ float xs[64][68];     // [row][k], padded

    int tid = threadIdx.x;
#pragma unroll
    for (int i = 0; i < 4; i++)
        ((float4*)Ws)[tid + 256 * i] = ((const float4*)W)[tid + 256 * i];

    int tx = tid & 15;   // col group
    int ty = tid >> 4;   // row group
    int r0 = ty * 4;
    int c0 = tx * 4;

    for (int tile = blockIdx.x; tile < N_TILES; tile += gridDim.x) {
        long long rowbase = (long long)tile * TILE_ROWS;
        __syncthreads();  // protect xs from previous iteration's readers
        // Stage 64x64 x-tile: 1024 float4 loads, 4 per thread
#pragma unroll
        for (int i = 0; i < 4; i++) {
            int f = tid + i * 256;          // 0..1023
            int r = f >> 4, kq = f & 15;
            long long grow = rowbase + r;
            float4 v = make_float4(0.f, 0.f, 0.f, 0.f);
            if (grow < N_NODES) v = *(const float4*)&x[grow * 64 + kq * 4];
            *(float4*)&xs[r][kq * 4] = v;
        }
        __syncthreads();

        unsigned long long a01[4], a23[4];
#pragma unroll
        for (int i = 0; i < 4; i++) { a01[i] = 0ull; a23[i] = 0ull; }

#pragma unroll
        for (int k0 = 0; k0 < 64; k0 += 4) {
            float4 xv[4];
#pragma unroll
            for (int i = 0; i < 4; i++) xv[i] = *(float4*)&xs[r0 + i][k0];
#pragma unroll
            for (int kk = 0; kk < 4; kk++) {
                float4 w = *(float4*)&Ws[(k0 + kk) * 64 + c0];
                unsigned long long w01 = pack2(w.x, w.y);
                unsigned long long w23 = pack2(w.z, w.w);
#pragma unroll
                for (int i = 0; i < 4; i++) {
                    float xk = (kk == 0) ? xv[i].x : (kk == 1) ? xv[i].y
                             : (kk == 2) ? xv[i].z : xv[i].w;
                    unsigned long long xx = pack2(xk, xk);
                    a01[i] = ffma2(xx, w01, a01[i]);
                    a23[i] = ffma2(xx, w23, a23[i]);
                }
            }
        }

#pragma unroll
        for (int i = 0; i < 4; i++) {
            long long row = rowbase + r0 + i;
            if (row < N_NODES) {
                float dinv = rsqrtf(g_deg[row]);
                float b0, b1, b2, b3;
                unpack2(a01[i], b0, b1);
                unpack2(a23[i], b2, b3);
                float4 o = make_float4(b0 * dinv, b1 * dinv, b2 * dinv, b3 * dinv);
                *(float4*)&g_h2[row * 64 + c0] = o;
                *(float4*)&g_acc[row * 64 + c0] = o;  // self-loop seed
            }
        }
    }
}

// ---------------------------------------------------------------------------
// K3: edge scatter — acc[dst] += h2[src]
// 16 lanes per edge: one LDG.128 gather + one red.global.add.v4.f32 per lane.
// ---------------------------------------------------------------------------
__global__ __launch_bounds__(256) void k_scatter(const int* __restrict__ ei) {
    long long tid = (long long)blockIdx.x * blockDim.x + threadIdx.x;
    int e = (int)(tid >> 4);
    int j = (int)(tid & 15);
    if (e >= N_EDGES) return;
    int src = ei[e];
    int dst = ei[N_EDGES + e];
    float4 v = *(const float4*)&g_h2[(long long)src * 64 + j * 4];
    float* p = &g_acc[(long long)dst * 64 + j * 4];
    asm volatile("red.global.add.v4.f32 [%0], {%1, %2, %3, %4};"
                 :: "l"(p), "f"(v.x), "f"(v.y), "f"(v.z), "f"(v.w)
                 : "memory");
}

// ---------------------------------------------------------------------------
// K4: fused epilogue. Phase 1: warp-per-row LayerNorm/ReLU/gate into smem
// (64 rows per block). Phase 2: register-tiled f32x2 GEMM2 (+fcb) -> out.
// ---------------------------------------------------------------------------
__global__ __launch_bounds__(256) void k_epi(const float* __restrict__ x,
                                             const float* __restrict__ b,
                                             const float* __restrict__ gamma,
                                             const float* __restrict__ beta,
                                             const float* __restrict__ fcW,
                                             const float* __restrict__ fcb,
                                             float* __restrict__ out) {
    __shared__ float Ws[64 * 64];    // fcW, k-major
    __shared__ float rs[64][68];     // gated LN output, [row][k]
    __shared__ float sb[64], sg[64], sbe[64], sfcb[64];

    int tid = threadIdx.x;
#pragma unroll
    for (int i = 0; i < 4; i++)
        ((float4*)Ws)[tid + 256 * i] = ((const float4*)fcW)[tid + 256 * i];
    if (tid < 64) {
        sb[tid] = b[tid];
        sg[tid] = gamma[tid];
        sbe[tid] = beta[tid];
        sfcb[tid] = fcb[tid];
    }

    int w = tid >> 5;    // warp id
    int l = tid & 31;    // lane
    int tx = tid & 15;
    int ty = tid >> 4;
    int r0 = ty * 4;
    int c0 = tx * 4;

    for (int tile = blockIdx.x; tile < N_TILES; tile += gridDim.x) {
        long long rowbase = (long long)tile * TILE_ROWS;
        __syncthreads();  // protect rs from previous iteration's phase 2

        // ---- Phase 1: LN + ReLU + gate; warp handles 8 rows ----
#pragma unroll
        for (int rr = 0; rr < 8; rr++) {
            int lr = w * 8 + rr;
            long long row = rowbase + lr;
            if (row < N_NODES) {
                float dinv = rsqrtf(g_deg[row]);
                long long base = row * 64;
                float2 av = *(const float2*)&g_acc[base + 2 * l];
                float v0 = av.x * dinv + sb[2 * l];
                float v1 = av.y * dinv + sb[2 * l + 1];

                float s = v0 + v1;
#pragma unroll
                for (int o = 16; o; o >>= 1) s += __shfl_xor_sync(0xFFFFFFFFu, s, o);
                float mu = s * (1.0f / 64.0f);

                float d0 = v0 - mu, d1 = v1 - mu;
                float q = d0 * d0 + d1 * d1;
#pragma unroll
                for (int o = 16; o; o >>= 1) q += __shfl_xor_sync(0xFFFFFFFFu, q, o);
                float inv = rsqrtf(q * (1.0f / 64.0f) + 1e-5f);

                float2 xv = *(const float2*)&x[base + 2 * l];
                float t0 = fmaxf(d0 * inv * sg[2 * l] + sbe[2 * l], 0.f) * xv.x;
                float t1 = fmaxf(d1 * inv * sg[2 * l + 1] + sbe[2 * l + 1], 0.f) * xv.y;
                rs[lr][2 * l] = t0;
                rs[lr][2 * l + 1] = t1;
            } else {
                rs[lr][2 * l] = 0.f;
                rs[lr][2 * l + 1] = 0.f;
            }
        }
        __syncthreads();

        // ---- Phase 2: out = rs @ fcW + fcb (register-tiled, f32x2) ----
        unsigned long long a01[4], a23[4];
#pragma unroll
        for (int i = 0; i < 4; i++) { a01[i] = 0ull; a23[i] = 0ull; }

#pragma unroll
        for (int k0 = 0; k0 < 64; k0 += 4) {
            float4 xv[4];
#pragma unroll
            for (int i = 0; i < 4; i++) xv[i] = *(float4*)&rs[r0 + i][k0];
#pragma unroll
            for (int kk = 0; kk < 4; kk++) {
                float4 wv = *(float4*)&Ws[(k0 + kk) * 64 + c0];
                unsigned long long w01 = pack2(wv.x, wv.y);
                unsigned long long w23 = pack2(wv.z, wv.w);
#pragma unroll
                for (int i = 0; i < 4; i++) {
                    float xk = (kk == 0) ? xv[i].x : (kk == 1) ? xv[i].y
                             : (kk == 2) ? xv[i].z : xv[i].w;
                    unsigned long long xx = pack2(xk, xk);
                    a01[i] = ffma2(xx, w01, a01[i]);
                    a23[i] = ffma2(xx, w23, a23[i]);
                }
            }
        }

#pragma unroll
        for (int i = 0; i < 4; i++) {
            long long row = rowbase + r0 + i;
            if (row < N_NODES) {
                float b0, b1, b2, b3;
                unpack2(a01[i], b0, b1);
                unpack2(a23[i], b2, b3);
                float4 o = make_float4(b0 + sfcb[c0], b1 + sfcb[c0 + 1],
                                       b2 + sfcb[c0 + 2], b3 + sfcb[c0 + 3]);
                *(float4*)&out[row * 64 + c0] = o;
            }
        }
    }
}

// ---------------------------------------------------------------------------
extern "C" void kernel_launch(void* const* d_in, const int* in_sizes, int n_in,
                              void* d_out, int out_size) {
    const float* x     = (const float*)d_in[0];
    const int*   ei    = (const int*)d_in[1];   // int32 per harness metadata
    const float* W     = (const float*)d_in[2];
    const float* b     = (const float*)d_in[3];
    const float* gamma = (const float*)d_in[4];
    const float* beta  = (const float*)d_in[5];
    const float* fcW   = (const float*)d_in[6];
    const float* fcb   = (const float*)d_in[7];
    float* out = (float*)d_out;

    (void)in_sizes; (void)n_in; (void)out_size;

    // K0: deg = 1
    k_init<<<(N_NODES + 255) / 256, 256>>>();
    // K1: degree count
    k_count<<<(N_EDGES + 255) / 256, 256>>>(ei);
    // K2: h2 = (x@W)*dinv, acc seeded with h2
    k_gemm1<<<592, 256>>>(x, W);
    // K3: edge scatter
    {
        long long threads = (long long)N_EDGES * 16;
        int blocks = (int)((threads + 255) / 256);
        k_scatter<<<blocks, 256>>>(ei);
    }
    // K4: fused epilogue
    k_epi<<<592, 256>>>(x, b, gamma, beta, fcW, fcb, out);
}

// round 6
// speedup vs baseline: 1.8874x; 1.2139x over previous
#include <cuda_runtime.h>
#include <cstdint>

#define N_NODES 100000
#define N_EDGES 800000
#define C 64

#define G1_ROWS 128
#define G1_TILES ((N_NODES + G1_ROWS - 1) / G1_ROWS)   // 782
#define EPI_ROWS 64
#define EPI_TILES ((N_NODES + EPI_ROWS - 1) / EPI_ROWS) // 1563

// Scratch (device globals — no allocation allowed in kernel_launch)
__device__ float g_h2[(size_t)N_NODES * C];   // (x@W) * dinv[row]
__device__ float g_acc[(size_t)N_NODES * C];  // accumulator, pre-seeded with h2 (self-loop)
__device__ float g_deg[N_NODES];              // degree (incl. self-loop)

// ---- Blackwell packed f32x2 helpers (FFMA2: 2 fp32 FMAs per issue) --------
__device__ __forceinline__ unsigned long long pack2(float lo, float hi) {
    unsigned long long r;
    asm("mov.b64 %0, {%1, %2};" : "=l"(r) : "f"(lo), "f"(hi));
    return r;
}
__device__ __forceinline__ void unpack2(unsigned long long v, float& lo, float& hi) {
    asm("mov.b64 {%0, %1}, %2;" : "=f"(lo), "=f"(hi) : "l"(v));
}
__device__ __forceinline__ unsigned long long ffma2(unsigned long long a,
                                                    unsigned long long b,
                                                    unsigned long long c) {
    unsigned long long d;
    asm("fma.rn.f32x2 %0, %1, %2, %3;" : "=l"(d) : "l"(a), "l"(b), "l"(c));
    return d;
}

// ---------------------------------------------------------------------------
// K0: deg = 1 (self loop). acc is NOT zeroed — gemm1 seeds it with h2.
// ---------------------------------------------------------------------------
__global__ void k_init() {
    int i = blockIdx.x * blockDim.x + threadIdx.x;
    if (i < N_NODES) g_deg[i] = 1.0f;
}

// ---------------------------------------------------------------------------
// K1: degree count over dst (edge_index arrives as int32 from the harness)
// ---------------------------------------------------------------------------
__global__ void k_count(const int* __restrict__ ei) {
    int e = blockIdx.x * blockDim.x + threadIdx.x;
    if (e < N_EDGES) {
        int dst = ei[N_EDGES + e];
        atomicAdd(&g_deg[dst], 1.0f);
    }
}

// ---------------------------------------------------------------------------
// K2: h2 = (x @ W) * rsqrt(deg); also seeds acc = h2 (self-loop term).
// One 128-row tile per block (782 blocks). 256 threads as 16x16; each thread
// computes an 8-row x 4-col micro-tile -> 12 LDS.128 : 64 FFMA2 per 4 k-steps
// (FMA-bound, 2.7x LDS headroom).
// ---------------------------------------------------------------------------
__global__ __launch_bounds__(256) void k_gemm1(const float* __restrict__ x,
                                               const float* __restrict__ W) {
    __shared__ float Ws[64 * 64];      // k-major: Ws[k*64 + col]
    __shared__ float xs[G1_ROWS][68];  // [row][k], padded

    int tid = threadIdx.x;
    long long rowbase = (long long)blockIdx.x * G1_ROWS;

    // Stage W: 1024 float4, 4 per thread
#pragma unroll
    for (int i = 0; i < 4; i++)
        ((float4*)Ws)[tid + 256 * i] = ((const float4*)W)[tid + 256 * i];

    // Stage 128x64 x-tile: 2048 float4, 8 per thread
#pragma unroll
    for (int i = 0; i < 8; i++) {
        int f = tid + i * 256;          // 0..2047
        int r = f >> 4, kq = f & 15;
        long long grow = rowbase + r;
        float4 v = make_float4(0.f, 0.f, 0.f, 0.f);
        if (grow < N_NODES) v = *(const float4*)&x[grow * 64 + kq * 4];
        *(float4*)&xs[r][kq * 4] = v;
    }
    __syncthreads();

    int tx = tid & 15;   // col group
    int ty = tid >> 4;   // row group
    int r0 = ty * 8;
    int c0 = tx * 4;

    unsigned long long a01[8], a23[8];
#pragma unroll
    for (int i = 0; i < 8; i++) { a01[i] = 0ull; a23[i] = 0ull; }

#pragma unroll
    for (int k0 = 0; k0 < 64; k0 += 4) {
        float4 xv[8];
#pragma unroll
        for (int i = 0; i < 8; i++) xv[i] = *(float4*)&xs[r0 + i][k0];
#pragma unroll
        for (int kk = 0; kk < 4; kk++) {
            float4 w = *(float4*)&Ws[(k0 + kk) * 64 + c0];
            unsigned long long w01 = pack2(w.x, w.y);
            unsigned long long w23 = pack2(w.z, w.w);
#pragma unroll
            for (int i = 0; i < 8; i++) {
                float xk = (kk == 0) ? xv[i].x : (kk == 1) ? xv[i].y
                         : (kk == 2) ? xv[i].z : xv[i].w;
                unsigned long long xx = pack2(xk, xk);
                a01[i] = ffma2(xx, w01, a01[i]);
                a23[i] = ffma2(xx, w23, a23[i]);
            }
        }
    }

#pragma unroll
    for (int i = 0; i < 8; i++) {
        long long row = rowbase + r0 + i;
        if (row < N_NODES) {
            float dinv = rsqrtf(g_deg[row]);
            float b0, b1, b2, b3;
            unpack2(a01[i], b0, b1);
            unpack2(a23[i], b2, b3);
            float4 o = make_float4(b0 * dinv, b1 * dinv, b2 * dinv, b3 * dinv);
            *(float4*)&g_h2[row * 64 + c0] = o;
            *(float4*)&g_acc[row * 64 + c0] = o;  // self-loop seed
        }
    }
}

// ---------------------------------------------------------------------------
// K3: edge scatter — acc[dst] += h2[src]
// 16 lanes per edge: one LDG.128 gather + one red.global.add.v4.f32 per lane.
// (At its L2-atomic throughput floor: ~50us across rounds.)
// ---------------------------------------------------------------------------
__global__ __launch_bounds__(256) void k_scatter(const int* __restrict__ ei) {
    long long tid = (long long)blockIdx.x * blockDim.x + threadIdx.x;
    int e = (int)(tid >> 4);
    int j = (int)(tid & 15);
    if (e >= N_EDGES) return;
    int src = ei[e];
    int dst = ei[N_EDGES + e];
    float4 v = *(const float4*)&g_h2[(long long)src * 64 + j * 4];
    float* p = &g_acc[(long long)dst * 64 + j * 4];
    asm volatile("red.global.add.v4.f32 [%0], {%1, %2, %3, %4};"
                 :: "l"(p), "f"(v.x), "f"(v.y), "f"(v.z), "f"(v.w)
                 : "memory");
}

// ---------------------------------------------------------------------------
// K4: fused epilogue, one 64-row tile per block (1563 blocks).
// Phase 1: warp-per-row LN with parallel sum/sumsq reductions (half the
// shuffle chain) + batched row loads. Phase 2: register-tiled f32x2 GEMM2.
// ---------------------------------------------------------------------------
__global__ __launch_bounds__(256) void k_epi(const float* __restrict__ x,
                                             const float* __restrict__ b,
                                             const float* __restrict__ gamma,
                                             const float* __restrict__ beta,
                                             const float* __restrict__ fcW,
                                             const float* __restrict__ fcb,
                                             float* __restrict__ out) {
    __shared__ float Ws[64 * 64];    // fcW, k-major
    __shared__ float rs[64][68];     // gated LN output, [row][k]
    __shared__ float sb[64], sg[64], sbe[64], sfcb[64];

    int tid = threadIdx.x;
    long long rowbase = (long long)blockIdx.x * EPI_ROWS;

#pragma unroll
    for (int i = 0; i < 4; i++)
        ((float4*)Ws)[tid + 256 * i] = ((const float4*)fcW)[tid + 256 * i];
    if (tid < 64) {
        sb[tid] = b[tid];
        sg[tid] = gamma[tid];
        sbe[tid] = beta[tid];
        sfcb[tid] = fcb[tid];
    }

    int w = tid >> 5;    // warp id
    int l = tid & 31;    // lane

    // ---- Phase 1: LN + ReLU + gate; warp handles 8 rows ----
    // Batch loads first for MLP.
    float2 av[8], xv2[8];
#pragma unroll
    for (int rr = 0; rr < 8; rr++) {
        int lr = w * 8 + rr;
        long long row = rowbase + lr;
        if (row < N_NODES) {
            av[rr]  = *(const float2*)&g_acc[row * 64 + 2 * l];
            xv2[rr] = *(const float2*)&x[row * 64 + 2 * l];
        } else {
            av[rr] = make_float2(0.f, 0.f);
            xv2[rr] = make_float2(0.f, 0.f);
        }
    }
    __syncthreads();  // sb/sg/sbe ready (also Ws for phase 2)

#pragma unroll
    for (int rr = 0; rr < 8; rr++) {
        int lr = w * 8 + rr;
        long long row = rowbase + lr;
        if (row < N_NODES) {
            float dinv = rsqrtf(g_deg[row]);
            float v0 = av[rr].x * dinv + sb[2 * l];
            float v1 = av[rr].y * dinv + sb[2 * l + 1];

            float s = v0 + v1;
            float q = v0 * v0 + v1 * v1;
#pragma unroll
            for (int o = 16; o; o >>= 1) {   // independent chains, overlap
                s += __shfl_xor_sync(0xFFFFFFFFu, s, o);
                q += __shfl_xor_sync(0xFFFFFFFFu, q, o);
            }
            float mu = s * (1.0f / 64.0f);
            float var = q * (1.0f / 64.0f) - mu * mu;
            float inv = rsqrtf(var + 1e-5f);

            float t0 = fmaxf((v0 - mu) * inv * sg[2 * l] + sbe[2 * l], 0.f) * xv2[rr].x;
            float t1 = fmaxf((v1 - mu) * inv * sg[2 * l + 1] + sbe[2 * l + 1], 0.f) * xv2[rr].y;
            rs[lr][2 * l] = t0;
            rs[lr][2 * l + 1] = t1;
        } else {
            rs[lr][2 * l] = 0.f;
            rs[lr][2 * l + 1] = 0.f;
        }
    }
    __syncthreads();

    // ---- Phase 2: out = rs @ fcW + fcb (register-tiled 4x4, f32x2) ----
    int tx = tid & 15;
    int ty = tid >> 4;
    int r0 = ty * 4;
    int c0 = tx * 4;

    unsigned long long a01[4], a23[4];
#pragma unroll
    for (int i = 0; i < 4; i++) { a01[i] = 0ull; a23[i] = 0ull; }

#pragma unroll
    for (int k0 = 0; k0 < 64; k0 += 4) {
        float4 xv[4];
#pragma unroll
        for (int i = 0; i < 4; i++) xv[i] = *(float4*)&rs[r0 + i][k0];
#pragma unroll
        for (int kk = 0; kk < 4; kk++) {
            float4 wv = *(float4*)&Ws[(k0 + kk) * 64 + c0];
            unsigned long long w01 = pack2(wv.x, wv.y);
            unsigned long long w23 = pack2(wv.z, wv.w);
#pragma unroll
            for (int i = 0; i < 4; i++) {
                float xk = (kk == 0) ? xv[i].x : (kk == 1) ? xv[i].y
                         : (kk == 2) ? xv[i].z : xv[i].w;
                unsigned long long xx = pack2(xk, xk);
                a01[i] = ffma2(xx, w01, a01[i]);
                a23[i] = ffma2(xx, w23, a23[i]);
            }
        }
    }

#pragma unroll
    for (int i = 0; i < 4; i++) {
        long long row = rowbase + r0 + i;
        if (row < N_NODES) {
            float b0, b1, b2, b3;
            unpack2(a01[i], b0, b1);
            unpack2(a23[i], b2, b3);
            float4 o = make_float4(b0 + sfcb[c0], b1 + sfcb[c0 + 1],
                                   b2 + sfcb[c0 + 2], b3 + sfcb[c0 + 3]);
            *(float4*)&out[row * 64 + c0] = o;
        }
    }
}

// ---------------------------------------------------------------------------
extern "C" void kernel_launch(void* const* d_in, const int* in_sizes, int n_in,
                              void* d_out, int out_size) {
    const float* x     = (const float*)d_in[0];
    const int*   ei    = (const int*)d_in[1];   // int32 per harness metadata
    const float* W     = (const float*)d_in[2];
    const float* b     = (const float*)d_in[3];
    const float* gamma = (const float*)d_in[4];
    const float* beta  = (const float*)d_in[5];
    const float* fcW   = (const float*)d_in[6];
    const float* fcb   = (const float*)d_in[7];
    float* out = (float*)d_out;

    (void)in_sizes; (void)n_in; (void)out_size;

    // K0: deg = 1
    k_init<<<(N_NODES + 255) / 256, 256>>>();
    // K1: degree count
    k_count<<<(N_EDGES + 255) / 256, 256>>>(ei);
    // K2: h2 = (x@W)*dinv, acc seeded with h2
    k_gemm1<<<G1_TILES, 256>>>(x, W);
    // K3: edge scatter
    {
        long long threads = (long long)N_EDGES * 16;
        int blocks = (int)((threads + 255) / 256);
        k_scatter<<<blocks, 256>>>(ei);
    }
    // K4: fused epilogue
    k_epi<<<EPI_TILES, 256>>>(x, b, gamma, beta, fcW, fcb, out);
}

// round 7
// speedup vs baseline: 1.9407x; 1.0282x over previous
#include <cuda_runtime.h>
#include <cstdint>

#define N_NODES 100000
#define N_EDGES 800000
#define C 64

#define NB_SCAN ((N_NODES + 255) / 256)   // 391 scan blocks
#define G1_ROWS 128
#define G1_TILES ((N_NODES + G1_ROWS - 1) / G1_ROWS)     // 782
#define EPI_ROWS 64
#define EPI_TILES ((N_NODES + EPI_ROWS - 1) / EPI_ROWS)  // 1563

// Scratch (device globals — no allocation allowed in kernel_launch)
__device__ float g_h2[(size_t)N_NODES * C];   // (x@W) * dinv[row]
__device__ float g_acc[(size_t)N_NODES * C];  // gathered sums (incl. self-loop)
__device__ int   g_cnt[N_NODES];              // in-degree (excl. self-loop)
__device__ float g_dinv[N_NODES];             // rsqrt(1 + cnt)
__device__ int   g_bsum[NB_SCAN];             // scan block sums
__device__ int   g_boff[NB_SCAN];             // scan block offsets
__device__ int   g_off[N_NODES];              // CSR row starts
__device__ int   g_cursor[N_NODES];           // bucket-fill cursors
__device__ int   g_srcs[N_EDGES];             // CSR column (src) indices

// ---- Blackwell packed f32x2 helpers (FFMA2: 2 fp32 FMAs per issue) --------
__device__ __forceinline__ unsigned long long pack2(float lo, float hi) {
    unsigned long long r;
    asm("mov.b64 %0, {%1, %2};" : "=l"(r) : "f"(lo), "f"(hi));
    return r;
}
__device__ __forceinline__ void unpack2(unsigned long long v, float& lo, float& hi) {
    asm("mov.b64 {%0, %1}, %2;" : "=f"(lo), "=f"(hi) : "l"(v));
}
__device__ __forceinline__ unsigned long long ffma2(unsigned long long a,
                                                    unsigned long long b,
                                                    unsigned long long c) {
    unsigned long long d;
    asm("fma.rn.f32x2 %0, %1, %2, %3;" : "=l"(d) : "l"(a), "l"(b), "l"(c));
    return d;
}

// ---------------------------------------------------------------------------
// K0: zero the degree histogram
// ---------------------------------------------------------------------------
__global__ void k_init() {
    int i = blockIdx.x * blockDim.x + threadIdx.x;
    if (i < N_NODES) g_cnt[i] = 0;
}

// ---------------------------------------------------------------------------
// K1: degree histogram over dst (int atomics)
// ---------------------------------------------------------------------------
__global__ void k_count(const int* __restrict__ ei) {
    int e = blockIdx.x * blockDim.x + threadIdx.x;
    if (e < N_EDGES) atomicAdd(&g_cnt[ei[N_EDGES + e]], 1);
}

// ---------------------------------------------------------------------------
// K2a: scan pass 1 — per-block sums of cnt
// ---------------------------------------------------------------------------
__global__ __launch_bounds__(256) void k_scan1() {
    __shared__ int r[256];
    int t = threadIdx.x;
    int i = blockIdx.x * 256 + t;
    r[t] = (i < N_NODES) ? g_cnt[i] : 0;
    __syncthreads();
#pragma unroll
    for (int o = 128; o; o >>= 1) {
        if (t < o) r[t] += r[t + o];
        __syncthreads();
    }
    if (t == 0) g_bsum[blockIdx.x] = r[0];
}

// ---------------------------------------------------------------------------
// K2b: scan pass 2 — single-block exclusive scan of the 391 block sums
// ---------------------------------------------------------------------------
__global__ __launch_bounds__(512) void k_scan2() {
    __shared__ int s[512];
    int t = threadIdx.x;
    int v = (t < NB_SCAN) ? g_bsum[t] : 0;
    s[t] = v;
    __syncthreads();
#pragma unroll
    for (int o = 1; o < 512; o <<= 1) {
        int y = (t >= o) ? s[t - o] : 0;
        __syncthreads();
        s[t] += y;
        __syncthreads();
    }
    if (t < NB_SCAN) g_boff[t] = s[t] - v;   // exclusive
}

// ---------------------------------------------------------------------------
// K2c: scan pass 3 — block-local exclusive scan + block offset -> CSR starts;
// also seeds cursors and writes dinv = rsqrt(1 + cnt).
// ---------------------------------------------------------------------------
__global__ __launch_bounds__(256) void k_scan3() {
    __shared__ int wsum[8], woff[8];
    int t = threadIdx.x;
    int lane = t & 31, wid = t >> 5;
    int i = blockIdx.x * 256 + t;
    int v = (i < N_NODES) ? g_cnt[i] : 0;

    // warp inclusive scan
    int xv = v;
#pragma unroll
    for (int o = 1; o < 32; o <<= 1) {
        int y = __shfl_up_sync(0xFFFFFFFFu, xv, o);
        if (lane >= o) xv += y;
    }
    if (lane == 31) wsum[wid] = xv;
    __syncthreads();
    if (wid == 0) {
        int s = (lane < 8) ? wsum[lane] : 0;
        int orig = s;
#pragma unroll
        for (int o = 1; o < 8; o <<= 1) {
            int y = __shfl_up_sync(0xFFFFFFFFu, s, o);
            if (lane >= o) s += y;
        }
        if (lane < 8) woff[lane] = s - orig;  // exclusive warp offsets
    }
    __syncthreads();

    if (i < N_NODES) {
        int off = g_boff[blockIdx.x] + woff[wid] + (xv - v);
        g_off[i] = off;
        g_cursor[i] = off;
        g_dinv[i] = rsqrtf(1.0f + (float)v);
    }
}

// ---------------------------------------------------------------------------
// K3: bucket fill — CSR column indices in arbitrary within-row order
// ---------------------------------------------------------------------------
__global__ void k_fill(const int* __restrict__ ei) {
    int e = blockIdx.x * blockDim.x + threadIdx.x;
    if (e < N_EDGES) {
        int dst = ei[N_EDGES + e];
        int pos = atomicAdd(&g_cursor[dst], 1);
        g_srcs[pos] = ei[e];
    }
}

// ---------------------------------------------------------------------------
// K4: h2 = (x @ W) * dinv. One 128-row tile per block; 8x4 micro-tile, f32x2.
// (No acc seed — the gather adds the self-loop term.)
// ---------------------------------------------------------------------------
__global__ __launch_bounds__(256) void k_gemm1(const float* __restrict__ x,
                                               const float* __restrict__ W) {
    __shared__ float Ws[64 * 64];      // k-major: Ws[k*64 + col]
    __shared__ float xs[G1_ROWS][68];  // [row][k], padded

    int tid = threadIdx.x;
    long long rowbase = (long long)blockIdx.x * G1_ROWS;

#pragma unroll
    for (int i = 0; i < 4; i++)
        ((float4*)Ws)[tid + 256 * i] = ((const float4*)W)[tid + 256 * i];

#pragma unroll
    for (int i = 0; i < 8; i++) {
        int f = tid + i * 256;
        int r = f >> 4, kq = f & 15;
        long long grow = rowbase + r;
        float4 v = make_float4(0.f, 0.f, 0.f, 0.f);
        if (grow < N_NODES) v = *(const float4*)&x[grow * 64 + kq * 4];
        *(float4*)&xs[r][kq * 4] = v;
    }
    __syncthreads();

    int tx = tid & 15;
    int ty = tid >> 4;
    int r0 = ty * 8;
    int c0 = tx * 4;

    unsigned long long a01[8], a23[8];
#pragma unroll
    for (int i = 0; i < 8; i++) { a01[i] = 0ull; a23[i] = 0ull; }

#pragma unroll
    for (int k0 = 0; k0 < 64; k0 += 4) {
        float4 xv[8];
#pragma unroll
        for (int i = 0; i < 8; i++) xv[i] = *(float4*)&xs[r0 + i][k0];
#pragma unroll
        for (int kk = 0; kk < 4; kk++) {
            float4 w = *(float4*)&Ws[(k0 + kk) * 64 + c0];
            unsigned long long w01 = pack2(w.x, w.y);
            unsigned long long w23 = pack2(w.z, w.w);
#pragma unroll
            for (int i = 0; i < 8; i++) {
                float xk = (kk == 0) ? xv[i].x : (kk == 1) ? xv[i].y
                         : (kk == 2) ? xv[i].z : xv[i].w;
                unsigned long long xx = pack2(xk, xk);
                a01[i] = ffma2(xx, w01, a01[i]);
                a23[i] = ffma2(xx, w23, a23[i]);
            }
        }
    }

#pragma unroll
    for (int i = 0; i < 8; i++) {
        long long row = rowbase + r0 + i;
        if (row < N_NODES) {
            float dinv = g_dinv[row];
            float b0, b1, b2, b3;
            unpack2(a01[i], b0, b1);
            unpack2(a23[i], b2, b3);
            *(float4*)&g_h2[row * 64 + c0] =
                make_float4(b0 * dinv, b1 * dinv, b2 * dinv, b3 * dinv);
        }
    }
}

// ---------------------------------------------------------------------------
// K5: pull-gather — acc[i] = h2[i] + sum_{e in CSR row i} h2[srcs[e]]
// Warp per node; lane owns a float2 slice. 2-deep pipelined L2 gathers,
// one plain 256B store per node (no atomics).
// ---------------------------------------------------------------------------
__global__ __launch_bounds__(256) void k_gather() {
    int node = blockIdx.x * 8 + (threadIdx.x >> 5);
    int l = threadIdx.x & 31;
    if (node >= N_NODES) return;

    int start = g_off[node];
    int deg = g_cnt[node];
    const float2* h2p = (const float2*)g_h2;

    float2 a = h2p[(long long)node * 32 + l];  // self-loop term
    int e = start, end = start + deg;
    for (; e + 1 < end; e += 2) {
        int s0 = g_srcs[e];
        int s1 = g_srcs[e + 1];
        float2 v0 = h2p[(long long)s0 * 32 + l];
        float2 v1 = h2p[(long long)s1 * 32 + l];
        a.x += v0.x + v1.x;
        a.y += v0.y + v1.y;
    }
    if (e < end) {
        int s = g_srcs[e];
        float2 v = h2p[(long long)s * 32 + l];
        a.x += v.x;
        a.y += v.y;
    }
    ((float2*)g_acc)[(long long)node * 32 + l] = a;
}

// ---------------------------------------------------------------------------
// K6: fused epilogue — gcn = acc*dinv + b, LN (parallel sum/sumsq), ReLU,
// gate by x, then register-tiled f32x2 GEMM2 (+fcb). 64-row tiles.
// ---------------------------------------------------------------------------
__global__ __launch_bounds__(256) void k_epi(const float* __restrict__ x,
                                             const float* __restrict__ b,
                                             const float* __restrict__ gamma,
                                             const float* __restrict__ beta,
                                             const float* __restrict__ fcW,
                                             const float* __restrict__ fcb,
                                             float* __restrict__ out) {
    __shared__ float Ws[64 * 64];
    __shared__ float rs[64][68];
    __shared__ float sb[64], sg[64], sbe[64], sfcb[64];

    int tid = threadIdx.x;
    long long rowbase = (long long)blockIdx.x * EPI_ROWS;

#pragma unroll
    for (int i = 0; i < 4; i++)
        ((float4*)Ws)[tid + 256 * i] = ((const float4*)fcW)[tid + 256 * i];
    if (tid < 64) {
        sb[tid] = b[tid];
        sg[tid] = gamma[tid];
        sbe[tid] = beta[tid];
        sfcb[tid] = fcb[tid];
    }

    int w = tid >> 5;
    int l = tid & 31;

    float2 av[8], xv2[8];
#pragma unroll
    for (int rr = 0; rr < 8; rr++) {
        int lr = w * 8 + rr;
        long long row = rowbase + lr;
        if (row < N_NODES) {
            av[rr]  = *(const float2*)&g_acc[row * 64 + 2 * l];
            xv2[rr] = *(const float2*)&x[row * 64 + 2 * l];
        } else {
            av[rr] = make_float2(0.f, 0.f);
            xv2[rr] = make_float2(0.f, 0.f);
        }
    }
    __syncthreads();

#pragma unroll
    for (int rr = 0; rr < 8; rr++) {
        int lr = w * 8 + rr;
        long long row = rowbase + lr;
        if (row < N_NODES) {
            float dinv = g_dinv[row];
            float v0 = av[rr].x * dinv + sb[2 * l];
            float v1 = av[rr].y * dinv + sb[2 * l + 1];

            float s = v0 + v1;
            float q = v0 * v0 + v1 * v1;
#pragma unroll
            for (int o = 16; o; o >>= 1) {
                s += __shfl_xor_sync(0xFFFFFFFFu, s, o);
                q += __shfl_xor_sync(0xFFFFFFFFu, q, o);
            }
            float mu = s * (1.0f / 64.0f);
            float var = q * (1.0f / 64.0f) - mu * mu;
            float inv = rsqrtf(var + 1e-5f);

            float t0 = fmaxf((v0 - mu) * inv * sg[2 * l] + sbe[2 * l], 0.f) * xv2[rr].x;
            float t1 = fmaxf((v1 - mu) * inv * sg[2 * l + 1] + sbe[2 * l + 1], 0.f) * xv2[rr].y;
            rs[lr][2 * l] = t0;
            rs[lr][2 * l + 1] = t1;
        } else {
            rs[lr][2 * l] = 0.f;
            rs[lr][2 * l + 1] = 0.f;
        }
    }
    __syncthreads();

    int tx = tid & 15;
    int ty = tid >> 4;
    int r0 = ty * 4;
    int c0 = tx * 4;

    unsigned long long a01[4], a23[4];
#pragma unroll
    for (int i = 0; i < 4; i++) { a01[i] = 0ull; a23[i] = 0ull; }

#pragma unroll
    for (int k0 = 0; k0 < 64; k0 += 4) {
        float4 xv[4];
#pragma unroll
        for (int i = 0; i < 4; i++) xv[i] = *(float4*)&rs[r0 + i][k0];
#pragma unroll
        for (int kk = 0; kk < 4; kk++) {
            float4 wv = *(float4*)&Ws[(k0 + kk) * 64 + c0];
            unsigned long long w01 = pack2(wv.x, wv.y);
            unsigned long long w23 = pack2(wv.z, wv.w);
#pragma unroll
            for (int i = 0; i < 4; i++) {
                float xk = (kk == 0) ? xv[i].x : (kk == 1) ? xv[i].y
                         : (kk == 2) ? xv[i].z : xv[i].w;
                unsigned long long xx = pack2(xk, xk);
                a01[i] = ffma2(xx, w01, a01[i]);
                a23[i] = ffma2(xx, w23, a23[i]);
            }
        }
    }

#pragma unroll
    for (int i = 0; i < 4; i++) {
        long long row = rowbase + r0 + i;
        if (row < N_NODES) {
            float b0, b1, b2, b3;
            unpack2(a01[i], b0, b1);
            unpack2(a23[i], b2, b3);
            *(float4*)&out[row * 64 + c0] =
                make_float4(b0 + sfcb[c0], b1 + sfcb[c0 + 1],
                            b2 + sfcb[c0 + 2], b3 + sfcb[c0 + 3]);
        }
    }
}

// ---------------------------------------------------------------------------
extern "C" void kernel_launch(void* const* d_in, const int* in_sizes, int n_in,
                              void* d_out, int out_size) {
    const float* x     = (const float*)d_in[0];
    const int*   ei    = (const int*)d_in[1];   // int32 per harness metadata
    const float* W     = (const float*)d_in[2];
    const float* b     = (const float*)d_in[3];
    const float* gamma = (const float*)d_in[4];
    const float* beta  = (const float*)d_in[5];
    const float* fcW   = (const float*)d_in[6];
    const float* fcb   = (const float*)d_in[7];
    float* out = (float*)d_out;

    (void)in_sizes; (void)n_in; (void)out_size;

    k_init<<<NB_SCAN, 256>>>();
    k_count<<<(N_EDGES + 255) / 256, 256>>>(ei);
    k_scan1<<<NB_SCAN, 256>>>();
    k_scan2<<<1, 512>>>();
    k_scan3<<<NB_SCAN, 256>>>();
    k_fill<<<(N_EDGES + 255) / 256, 256>>>(ei);
    k_gemm1<<<G1_TILES, 256>>>(x, W);
    k_gather<<<(N_NODES + 7) / 8, 256>>>();
    k_epi<<<EPI_TILES, 256>>>(x, b, gamma, beta, fcW, fcb, out);
}

// round 8
// speedup vs baseline: 2.0348x; 1.0485x over previous
#include <cuda_runtime.h>
#include <cuda_fp16.h>
#include <cstdint>

#define N_NODES 100000
#define N_EDGES 800000
#define C 64

#define NB_INIT ((N_NODES + 255) / 256)          // 391
#define SCAN_CHUNK 1024
#define NB_SCAN ((N_NODES + SCAN_CHUNK - 1) / SCAN_CHUNK)  // 98
#define G1_ROWS 128
#define G1_TILES ((N_NODES + G1_ROWS - 1) / G1_ROWS)       // 782
#define EPI_ROWS 64
#define EPI_TILES ((N_NODES + EPI_ROWS - 1) / EPI_ROWS)    // 1563

// Scratch (device globals — no allocation allowed in kernel_launch)
__device__ __half2 g_h2h[(size_t)N_NODES * 32]; // (x@W)*dinv, fp16x2 (12.8MB)
__device__ int     g_cnt[N_NODES];              // in-degree (excl. self-loop)
__device__ float   g_dinv[N_NODES];             // rsqrt(1 + cnt)
__device__ int     g_bsum[NB_SCAN];             // scan block sums
__device__ int     g_boff[NB_SCAN];             // scan block offsets
__device__ int     g_off[N_NODES];              // CSR row starts
__device__ int     g_cursor[N_NODES];           // bucket-fill cursors
__device__ int     g_srcs[N_EDGES];             // CSR column (src) indices

// ---- Blackwell packed f32x2 helpers (FFMA2: 2 fp32 FMAs per issue) --------
__device__ __forceinline__ unsigned long long pack2(float lo, float hi) {
    unsigned long long r;
    asm("mov.b64 %0, {%1, %2};" : "=l"(r) : "f"(lo), "f"(hi));
    return r;
}
__device__ __forceinline__ void unpack2(unsigned long long v, float& lo, float& hi) {
    asm("mov.b64 {%0, %1}, %2;" : "=f"(lo), "=f"(hi) : "l"(v));
}
__device__ __forceinline__ unsigned long long ffma2(unsigned long long a,
                                                    unsigned long long b,
                                                    unsigned long long c) {
    unsigned long long d;
    asm("fma.rn.f32x2 %0, %1, %2, %3;" : "=l"(d) : "l"(a), "l"(b), "l"(c));
    return d;
}

// ---------------------------------------------------------------------------
// K0: zero the degree histogram
// ---------------------------------------------------------------------------
__global__ void k_init() {
    int i = blockIdx.x * blockDim.x + threadIdx.x;
    if (i < N_NODES) g_cnt[i] = 0;
}

// ---------------------------------------------------------------------------
// K1: degree histogram over dst (int atomics)
// ---------------------------------------------------------------------------
__global__ void k_count(const int* __restrict__ ei) {
    int e = blockIdx.x * blockDim.x + threadIdx.x;
    if (e < N_EDGES) atomicAdd(&g_cnt[ei[N_EDGES + e]], 1);
}

// ---------------------------------------------------------------------------
// K2a: per-1024-chunk sums (256 threads x 4 elems)
// ---------------------------------------------------------------------------
__global__ __launch_bounds__(256) void k_scan1() {
    __shared__ int wsum[8];
    int tid = threadIdx.x;
    int base = blockIdx.x * SCAN_CHUNK + tid * 4;
    int s = 0;
    if (base + 3 < N_NODES) {
        int4 v = *(const int4*)&g_cnt[base];
        s = v.x + v.y + v.z + v.w;
    } else {
#pragma unroll
        for (int j = 0; j < 4; j++)
            if (base + j < N_NODES) s += g_cnt[base + j];
    }
#pragma unroll
    for (int o = 16; o; o >>= 1) s += __shfl_down_sync(0xFFFFFFFFu, s, o);
    if ((tid & 31) == 0) wsum[tid >> 5] = s;
    __syncthreads();
    if (tid == 0) {
        int t = 0;
#pragma unroll
        for (int i = 0; i < 8; i++) t += wsum[i];
        g_bsum[blockIdx.x] = t;
    }
}

// ---------------------------------------------------------------------------
// K2b: single-warp exclusive scan of the 98 chunk sums
// ---------------------------------------------------------------------------
__global__ void k_scan2() {
    int l = threadIdx.x;   // 32 threads
    int vals[4];
    int tsum = 0;
#pragma unroll
    for (int j = 0; j < 4; j++) {
        int idx = l * 4 + j;
        int v = (idx < NB_SCAN) ? g_bsum[idx] : 0;
        vals[j] = v;
        tsum += v;
    }
    int inc = tsum;
#pragma unroll
    for (int o = 1; o < 32; o <<= 1) {
        int y = __shfl_up_sync(0xFFFFFFFFu, inc, o);
        if (l >= o) inc += y;
    }
    int run = inc - tsum;  // exclusive base for this lane's chunk
#pragma unroll
    for (int j = 0; j < 4; j++) {
        int idx = l * 4 + j;
        if (idx < NB_SCAN) g_boff[idx] = run;
        run += vals[j];
    }
}

// ---------------------------------------------------------------------------
// K2c: final scan — CSR starts, cursors, dinv. 1024 elems per block,
// thread handles 4 consecutive; register-local prefix + warp/block scan.
// ---------------------------------------------------------------------------
__global__ __launch_bounds__(256) void k_scan3() {
    __shared__ int wsum[8], woff[8];
    int tid = threadIdx.x;
    int lane = tid & 31, wid = tid >> 5;
    int base = blockIdx.x * SCAN_CHUNK + tid * 4;

    int v[4];
    if (base + 3 < N_NODES) {
        int4 t = *(const int4*)&g_cnt[base];
        v[0] = t.x; v[1] = t.y; v[2] = t.z; v[3] = t.w;
    } else {
#pragma unroll
        for (int j = 0; j < 4; j++)
            v[j] = (base + j < N_NODES) ? g_cnt[base + j] : 0;
    }
    int tsum = v[0] + v[1] + v[2] + v[3];

    int inc = tsum;
#pragma unroll
    for (int o = 1; o < 32; o <<= 1) {
        int y = __shfl_up_sync(0xFFFFFFFFu, inc, o);
        if (lane >= o) inc += y;
    }
    if (lane == 31) wsum[wid] = inc;
    __syncthreads();
    if (wid == 0) {
        int s = (lane < 8) ? wsum[lane] : 0;
        int orig = s;
#pragma unroll
        for (int o = 1; o < 8; o <<= 1) {
            int y = __shfl_up_sync(0xFFFFFFFFu, s, o);
            if (lane >= o) s += y;
        }
        if (lane < 8) woff[lane] = s - orig;
    }
    __syncthreads();

    int off = g_boff[blockIdx.x] + woff[wid] + (inc - tsum);
#pragma unroll
    for (int j = 0; j < 4; j++) {
        int i = base + j;
        if (i < N_NODES) {
            g_off[i] = off;
            g_cursor[i] = off;
            g_dinv[i] = rsqrtf(1.0f + (float)v[j]);
        }
        off += v[j];
    }
}

// ---------------------------------------------------------------------------
// K3: bucket fill — CSR column indices (within-row order arbitrary)
// ---------------------------------------------------------------------------
__global__ void k_fill(const int* __restrict__ ei) {
    int e = blockIdx.x * blockDim.x + threadIdx.x;
    if (e < N_EDGES) {
        int dst = ei[N_EDGES + e];
        int pos = atomicAdd(&g_cursor[dst], 1);
        g_srcs[pos] = ei[e];
    }
}

// ---------------------------------------------------------------------------
// K4: h2 = (x @ W) * dinv -> fp16x2. 128-row tiles, 8x4 micro-tile, f32x2.
// ---------------------------------------------------------------------------
__global__ __launch_bounds__(256) void k_gemm1(const float* __restrict__ x,
                                               const float* __restrict__ W) {
    __shared__ float Ws[64 * 64];      // k-major
    __shared__ float xs[G1_ROWS][68];

    int tid = threadIdx.x;
    long long rowbase = (long long)blockIdx.x * G1_ROWS;

#pragma unroll
    for (int i = 0; i < 4; i++)
        ((float4*)Ws)[tid + 256 * i] = ((const float4*)W)[tid + 256 * i];

#pragma unroll
    for (int i = 0; i < 8; i++) {
        int f = tid + i * 256;
        int r = f >> 4, kq = f & 15;
        long long grow = rowbase + r;
        float4 v = make_float4(0.f, 0.f, 0.f, 0.f);
        if (grow < N_NODES) v = *(const float4*)&x[grow * 64 + kq * 4];
        *(float4*)&xs[r][kq * 4] = v;
    }
    __syncthreads();

    int tx = tid & 15;
    int ty = tid >> 4;
    int r0 = ty * 8;
    int c0 = tx * 4;

    unsigned long long a01[8], a23[8];
#pragma unroll
    for (int i = 0; i < 8; i++) { a01[i] = 0ull; a23[i] = 0ull; }

#pragma unroll
    for (int k0 = 0; k0 < 64; k0 += 4) {
        float4 xv[8];
#pragma unroll
        for (int i = 0; i < 8; i++) xv[i] = *(float4*)&xs[r0 + i][k0];
#pragma unroll
        for (int kk = 0; kk < 4; kk++) {
            float4 w = *(float4*)&Ws[(k0 + kk) * 64 + c0];
            unsigned long long w01 = pack2(w.x, w.y);
            unsigned long long w23 = pack2(w.z, w.w);
#pragma unroll
            for (int i = 0; i < 8; i++) {
                float xk = (kk == 0) ? xv[i].x : (kk == 1) ? xv[i].y
                         : (kk == 2) ? xv[i].z : xv[i].w;
                unsigned long long xx = pack2(xk, xk);
                a01[i] = ffma2(xx, w01, a01[i]);
                a23[i] = ffma2(xx, w23, a23[i]);
            }
        }
    }

#pragma unroll
    for (int i = 0; i < 8; i++) {
        long long row = rowbase + r0 + i;
        if (row < N_NODES) {
            float dinv = g_dinv[row];
            float b0, b1, b2, b3;
            unpack2(a01[i], b0, b1);
            unpack2(a23[i], b2, b3);
            __half2 h01 = __floats2half2_rn(b0 * dinv, b1 * dinv);
            __half2 h23 = __floats2half2_rn(b2 * dinv, b3 * dinv);
            __half2* dst = &g_h2h[row * 32 + (c0 >> 1)];
            dst[0] = h01;
            dst[1] = h23;
        }
    }
}

// ---------------------------------------------------------------------------
// K5: fused gather + epilogue. Block = 64 nodes; 8 warps x 8 nodes each.
// Warp gathers one node's neighbor sum (fp16 payload, fp32 accum), does LN +
// ReLU + x-gate in registers, stages into smem; then register-tiled GEMM2.
// ---------------------------------------------------------------------------
__global__ __launch_bounds__(256) void k_gather_epi(
        const float* __restrict__ x,
        const float* __restrict__ b,
        const float* __restrict__ gamma,
        const float* __restrict__ beta,
        const float* __restrict__ fcW,
        const float* __restrict__ fcb,
        float* __restrict__ out) {
    __shared__ float Ws[64 * 64];
    __shared__ float rs[64][68];
    __shared__ float sb[64], sg[64], sbe[64], sfcb[64];

    int tid = threadIdx.x;
    long long rowbase = (long long)blockIdx.x * EPI_ROWS;

#pragma unroll
    for (int i = 0; i < 4; i++)
        ((float4*)Ws)[tid + 256 * i] = ((const float4*)fcW)[tid + 256 * i];
    if (tid < 64) {
        sb[tid] = b[tid];
        sg[tid] = gamma[tid];
        sbe[tid] = beta[tid];
        sfcb[tid] = fcb[tid];
    }
    __syncthreads();

    int w = tid >> 5;
    int l = tid & 31;

#pragma unroll
    for (int rr = 0; rr < 8; rr++) {
        int lr = w * 8 + rr;
        long long row = rowbase + lr;
        if (row < N_NODES) {
            int start = g_off[row];
            int deg = g_cnt[row];
            // self-loop term
            float2 a = __half22float2(g_h2h[row * 32 + l]);
            int e = start, end = start + deg;
            for (; e + 1 < end; e += 2) {
                int s0 = g_srcs[e];
                int s1 = g_srcs[e + 1];
                float2 v0 = __half22float2(g_h2h[(long long)s0 * 32 + l]);
                float2 v1 = __half22float2(g_h2h[(long long)s1 * 32 + l]);
                a.x += v0.x + v1.x;
                a.y += v0.y + v1.y;
            }
            if (e < end) {
                float2 v = __half22float2(g_h2h[(long long)g_srcs[e] * 32 + l]);
                a.x += v.x;
                a.y += v.y;
            }

            float dinv = g_dinv[row];
            float v0 = a.x * dinv + sb[2 * l];
            float v1 = a.y * dinv + sb[2 * l + 1];

            float s = v0 + v1;
            float q = v0 * v0 + v1 * v1;
#pragma unroll
            for (int o = 16; o; o >>= 1) {
                s += __shfl_xor_sync(0xFFFFFFFFu, s, o);
                q += __shfl_xor_sync(0xFFFFFFFFu, q, o);
            }
            float mu = s * (1.0f / 64.0f);
            float var = q * (1.0f / 64.0f) - mu * mu;
            float inv = rsqrtf(var + 1e-5f);

            float2 xv = *(const float2*)&x[row * 64 + 2 * l];
            rs[lr][2 * l]     = fmaxf((v0 - mu) * inv * sg[2 * l]     + sbe[2 * l],     0.f) * xv.x;
            rs[lr][2 * l + 1] = fmaxf((v1 - mu) * inv * sg[2 * l + 1] + sbe[2 * l + 1], 0.f) * xv.y;
        } else {
            rs[lr][2 * l] = 0.f;
            rs[lr][2 * l + 1] = 0.f;
        }
    }
    __syncthreads();

    // ---- GEMM2: out = rs @ fcW + fcb (register-tiled 4x4, f32x2) ----
    int tx = tid & 15;
    int ty = tid >> 4;
    int r0 = ty * 4;
    int c0 = tx * 4;

    unsigned long long a01[4], a23[4];
#pragma unroll
    for (int i = 0; i < 4; i++) { a01[i] = 0ull; a23[i] = 0ull; }

#pragma unroll
    for (int k0 = 0; k0 < 64; k0 += 4) {
        float4 xv[4];
#pragma unroll
        for (int i = 0; i < 4; i++) xv[i] = *(float4*)&rs[r0 + i][k0];
#pragma unroll
        for (int kk = 0; kk < 4; kk++) {
            float4 wv = *(float4*)&Ws[(k0 + kk) * 64 + c0];
            unsigned long long w01 = pack2(wv.x, wv.y);
            unsigned long long w23 = pack2(wv.z, wv.w);
#pragma unroll
            for (int i = 0; i < 4; i++) {
                float xk = (kk == 0) ? xv[i].x : (kk == 1) ? xv[i].y
                         : (kk == 2) ? xv[i].z : xv[i].w;
                unsigned long long xx = pack2(xk, xk);
                a01[i] = ffma2(xx, w01, a01[i]);
                a23[i] = ffma2(xx, w23, a23[i]);
            }
        }
    }

#pragma unroll
    for (int i = 0; i < 4; i++) {
        long long row = rowbase + r0 + i;
        if (row < N_NODES) {
            float b0, b1, b2, b3;
            unpack2(a01[i], b0, b1);
            unpack2(a23[i], b2, b3);
            *(float4*)&out[row * 64 + c0] =
                make_float4(b0 + sfcb[c0], b1 + sfcb[c0 + 1],
                            b2 + sfcb[c0 + 2], b3 + sfcb[c0 + 3]);
        }
    }
}

// ---------------------------------------------------------------------------
extern "C" void kernel_launch(void* const* d_in, const int* in_sizes, int n_in,
                              void* d_out, int out_size) {
    const float* x     = (const float*)d_in[0];
    const int*   ei    = (const int*)d_in[1];   // int32 per harness metadata
    const float* W     = (const float*)d_in[2];
    const float* b     = (const float*)d_in[3];
    const float* gamma = (const float*)d_in[4];
    const float* beta  = (const float*)d_in[5];
    const float* fcW   = (const float*)d_in[6];
    const float* fcb   = (const float*)d_in[7];
    float* out = (float*)d_out;

    (void)in_sizes; (void)n_in; (void)out_size;

    k_init<<<NB_INIT, 256>>>();
    k_count<<<(N_EDGES + 255) / 256, 256>>>(ei);
    k_scan1<<<NB_SCAN, 256>>>();
    k_scan2<<<1, 32>>>();
    k_scan3<<<NB_SCAN, 256>>>();
    k_fill<<<(N_EDGES + 255) / 256, 256>>>(ei);
    k_gemm1<<<G1_TILES, 256>>>(x, W);
    k_gather_epi<<<EPI_TILES, 256>>>(x, b, gamma, beta, fcW, fcb, out);
}

// round 9
// speedup vs baseline: 2.0863x; 1.0253x over previous
#include <cuda_runtime.h>
#include <cuda_fp16.h>
#include <cstdint>

#define N_NODES 100000
#define N_EDGES 800000
#define C 64

#define SCAN_CHUNK 1024
#define NB_SCAN ((N_NODES + SCAN_CHUNK - 1) / SCAN_CHUNK)  // 98
#define G1_ROWS 128
#define G1_TILES ((N_NODES + G1_ROWS - 1) / G1_ROWS)       // 782
#define COUNT_BLOCKS ((N_EDGES / 4 + 255) / 256)           // 782
#define EPI_ROWS 64
#define EPI_TILES ((N_NODES + EPI_ROWS - 1) / EPI_ROWS)    // 1563

// Scratch (device globals — zero-initialized at module load; g_cnt's
// "zero on entry" invariant is restored by k_gather_epi every run)
__device__ __half2 g_hh[(size_t)N_NODES * 32]; // x@W UNSCALED, fp16x2 (12.8MB)
__device__ int     g_cnt[N_NODES];             // in-degree (excl. self-loop)
__device__ float   g_dinv[N_NODES];            // rsqrt(1 + cnt)
__device__ int     g_bsum[NB_SCAN];            // scan chunk sums
__device__ int     g_off[N_NODES];             // CSR row starts
__device__ int     g_cursor[N_NODES];          // bucket-fill cursors
__device__ int     g_srcs[N_EDGES];            // CSR column (src) indices

// ---- Blackwell packed f32x2 helpers (FFMA2: 2 fp32 FMAs per issue) --------
__device__ __forceinline__ unsigned long long pack2(float lo, float hi) {
    unsigned long long r;
    asm("mov.b64 %0, {%1, %2};" : "=l"(r) : "f"(lo), "f"(hi));
    return r;
}
__device__ __forceinline__ void unpack2(unsigned long long v, float& lo, float& hi) {
    asm("mov.b64 {%0, %1}, %2;" : "=f"(lo), "=f"(hi) : "l"(v));
}
__device__ __forceinline__ unsigned long long ffma2(unsigned long long a,
                                                    unsigned long long b,
                                                    unsigned long long c) {
    unsigned long long d;
    asm("fma.rn.f32x2 %0, %1, %2, %3;" : "=l"(d) : "l"(a), "l"(b), "l"(c));
    return d;
}

// ---------------------------------------------------------------------------
// K1: merged GEMM1 + degree count.
// Blocks [0, G1_TILES): hh = x @ W (UNSCALED) -> fp16, 8x4 micro-tile, f32x2.
// Blocks [G1_TILES, +COUNT_BLOCKS): histogram over dst, 4 edges/thread.
// The two halves are independent; FMA-bound GEMM overlaps atomic-bound count.
// ---------------------------------------------------------------------------
__global__ __launch_bounds__(256) void k_count_gemm(const float* __restrict__ x,
                                                    const float* __restrict__ W,
                                                    const int* __restrict__ ei) {
    __shared__ float Ws[64 * 64];      // k-major
    __shared__ float xs[G1_ROWS][68];

    int tid = threadIdx.x;

    if (blockIdx.x >= G1_TILES) {
        // ---- count part ----
        int idx = (blockIdx.x - G1_TILES) * 256 + tid;   // edge quad index
        int e4 = idx * 4;
        if (e4 + 3 < N_EDGES) {
            int4 d = *(const int4*)&ei[N_EDGES + e4];
            atomicAdd(&g_cnt[d.x], 1);
            atomicAdd(&g_cnt[d.y], 1);
            atomicAdd(&g_cnt[d.z], 1);
            atomicAdd(&g_cnt[d.w], 1);
        } else {
            for (int j = 0; j < 4; j++)
                if (e4 + j < N_EDGES) atomicAdd(&g_cnt[ei[N_EDGES + e4 + j]], 1);
        }
        return;
    }

    // ---- GEMM part ----
    long long rowbase = (long long)blockIdx.x * G1_ROWS;

#pragma unroll
    for (int i = 0; i < 4; i++)
        ((float4*)Ws)[tid + 256 * i] = ((const float4*)W)[tid + 256 * i];

#pragma unroll
    for (int i = 0; i < 8; i++) {
        int f = tid + i * 256;
        int r = f >> 4, kq = f & 15;
        long long grow = rowbase + r;
        float4 v = make_float4(0.f, 0.f, 0.f, 0.f);
        if (grow < N_NODES) v = *(const float4*)&x[grow * 64 + kq * 4];
        *(float4*)&xs[r][kq * 4] = v;
    }
    __syncthreads();

    int tx = tid & 15;
    int ty = tid >> 4;
    int r0 = ty * 8;
    int c0 = tx * 4;

    unsigned long long a01[8], a23[8];
#pragma unroll
    for (int i = 0; i < 8; i++) { a01[i] = 0ull; a23[i] = 0ull; }

#pragma unroll
    for (int k0 = 0; k0 < 64; k0 += 4) {
        float4 xv[8];
#pragma unroll
        for (int i = 0; i < 8; i++) xv[i] = *(float4*)&xs[r0 + i][k0];
#pragma unroll
        for (int kk = 0; kk < 4; kk++) {
            float4 w = *(float4*)&Ws[(k0 + kk) * 64 + c0];
            unsigned long long w01 = pack2(w.x, w.y);
            unsigned long long w23 = pack2(w.z, w.w);
#pragma unroll
            for (int i = 0; i < 8; i++) {
                float xk = (kk == 0) ? xv[i].x : (kk == 1) ? xv[i].y
                         : (kk == 2) ? xv[i].z : xv[i].w;
                unsigned long long xx = pack2(xk, xk);
                a01[i] = ffma2(xx, w01, a01[i]);
                a23[i] = ffma2(xx, w23, a23[i]);
            }
        }
    }

#pragma unroll
    for (int i = 0; i < 8; i++) {
        long long row = rowbase + r0 + i;
        if (row < N_NODES) {
            float b0, b1, b2, b3;
            unpack2(a01[i], b0, b1);
            unpack2(a23[i], b2, b3);
            __half2* dst = &g_hh[row * 32 + (c0 >> 1)];
            dst[0] = __floats2half2_rn(b0, b1);
            dst[1] = __floats2half2_rn(b2, b3);
        }
    }
}

// ---------------------------------------------------------------------------
// K2: per-1024-chunk sums of cnt (256 threads x 4 elems)
// ---------------------------------------------------------------------------
__global__ __launch_bounds__(256) void k_scan1() {
    __shared__ int wsum[8];
    int tid = threadIdx.x;
    int base = blockIdx.x * SCAN_CHUNK + tid * 4;
    int s = 0;
    if (base + 3 < N_NODES) {
        int4 v = *(const int4*)&g_cnt[base];
        s = v.x + v.y + v.z + v.w;
    } else {
#pragma unroll
        for (int j = 0; j < 4; j++)
            if (base + j < N_NODES) s += g_cnt[base + j];
    }
#pragma unroll
    for (int o = 16; o; o >>= 1) s += __shfl_down_sync(0xFFFFFFFFu, s, o);
    if ((tid & 31) == 0) wsum[tid >> 5] = s;
    __syncthreads();
    if (tid == 0) {
        int t = 0;
#pragma unroll
        for (int i = 0; i < 8; i++) t += wsum[i];
        g_bsum[blockIdx.x] = t;
    }
}

// ---------------------------------------------------------------------------
// K3: final scan. Warp 0 of each block redundantly warp-scans the 98 chunk
// sums to get this block's base (kills the separate scan2 launch), then
// block-local scan -> CSR starts, cursors, dinv.
// ---------------------------------------------------------------------------
__global__ __launch_bounds__(256) void k_scan23() {
    __shared__ int wsum[8], woff[8];
    __shared__ int blockbase;
    int tid = threadIdx.x;
    int lane = tid & 31, wid = tid >> 5;

    if (wid == 0) {
        // exclusive prefix of g_bsum at index blockIdx.x
        int vals[4];
        int tsum = 0;
#pragma unroll
        for (int j = 0; j < 4; j++) {
            int idx = lane * 4 + j;
            int v = (idx < NB_SCAN) ? g_bsum[idx] : 0;
            vals[j] = v;
            tsum += v;
        }
        int inc = tsum;
#pragma unroll
        for (int o = 1; o < 32; o <<= 1) {
            int y = __shfl_up_sync(0xFFFFFFFFu, inc, o);
            if (lane >= o) inc += y;
        }
        int run = inc - tsum;
#pragma unroll
        for (int j = 0; j < 4; j++) {
            int idx = lane * 4 + j;
            if (idx == (int)blockIdx.x) blockbase = run;
            run += vals[j];
        }
    }

    int base = blockIdx.x * SCAN_CHUNK + tid * 4;
    int v[4];
    if (base + 3 < N_NODES) {
        int4 t = *(const int4*)&g_cnt[base];
        v[0] = t.x; v[1] = t.y; v[2] = t.z; v[3] = t.w;
    } else {
#pragma unroll
        for (int j = 0; j < 4; j++)
            v[j] = (base + j < N_NODES) ? g_cnt[base + j] : 0;
    }
    int tsum = v[0] + v[1] + v[2] + v[3];

    int inc = tsum;
#pragma unroll
    for (int o = 1; o < 32; o <<= 1) {
        int y = __shfl_up_sync(0xFFFFFFFFu, inc, o);
        if (lane >= o) inc += y;
    }
    if (lane == 31) wsum[wid] = inc;
    __syncthreads();
    if (wid == 0) {
        int s = (lane < 8) ? wsum[lane] : 0;
        int orig = s;
#pragma unroll
        for (int o = 1; o < 8; o <<= 1) {
            int y = __shfl_up_sync(0xFFFFFFFFu, s, o);
            if (lane >= o) s += y;
        }
        if (lane < 8) woff[lane] = s - orig;
    }
    __syncthreads();

    int off = blockbase + woff[wid] + (inc - tsum);
#pragma unroll
    for (int j = 0; j < 4; j++) {
        int i = base + j;
        if (i < N_NODES) {
            g_off[i] = off;
            g_cursor[i] = off;
            g_dinv[i] = rsqrtf(1.0f + (float)v[j]);
        }
        off += v[j];
    }
}

// ---------------------------------------------------------------------------
// K4: bucket fill — 4 edges per thread (int4 index loads)
// ---------------------------------------------------------------------------
__global__ __launch_bounds__(256) void k_fill(const int* __restrict__ ei) {
    int idx = blockIdx.x * 256 + threadIdx.x;
    int e4 = idx * 4;
    if (e4 + 3 < N_EDGES) {
        int4 s = *(const int4*)&ei[e4];
        int4 d = *(const int4*)&ei[N_EDGES + e4];
        g_srcs[atomicAdd(&g_cursor[d.x], 1)] = s.x;
        g_srcs[atomicAdd(&g_cursor[d.y], 1)] = s.y;
        g_srcs[atomicAdd(&g_cursor[d.z], 1)] = s.z;
        g_srcs[atomicAdd(&g_cursor[d.w], 1)] = s.w;
    } else {
        for (int j = 0; j < 4; j++)
            if (e4 + j < N_EDGES) {
                int dst = ei[N_EDGES + e4 + j];
                g_srcs[atomicAdd(&g_cursor[dst], 1)] = ei[e4 + j];
            }
    }
}

// ---------------------------------------------------------------------------
// K5: fused gather + epilogue. Block = 64 nodes; 8 warps x 8 nodes.
// Gather: a = h[row]*dinv[row] + sum h[src]*dinv[src]; gcn = a*dinv[row] + b.
// Then LN + ReLU + x-gate into smem; register-tiled f32x2 GEMM2.
// Also restores the g_cnt==0 invariant for the next run.
// ---------------------------------------------------------------------------
__global__ __launch_bounds__(256) void k_gather_epi(
        const float* __restrict__ x,
        const float* __restrict__ b,
        const float* __restrict__ gamma,
        const float* __restrict__ beta,
        const float* __restrict__ fcW,
        const float* __restrict__ fcb,
        float* __restrict__ out) {
    __shared__ float Ws[64 * 64];
    __shared__ float rs[64][68];
    __shared__ float sb[64], sg[64], sbe[64], sfcb[64];

    int tid = threadIdx.x;
    long long rowbase = (long long)blockIdx.x * EPI_ROWS;

#pragma unroll
    for (int i = 0; i < 4; i++)
        ((float4*)Ws)[tid + 256 * i] = ((const float4*)fcW)[tid + 256 * i];
    if (tid < 64) {
        sb[tid] = b[tid];
        sg[tid] = gamma[tid];
        sbe[tid] = beta[tid];
        sfcb[tid] = fcb[tid];
    }
    __syncthreads();

    int w = tid >> 5;
    int l = tid & 31;

#pragma unroll
    for (int rr = 0; rr < 8; rr++) {
        int lr = w * 8 + rr;
        long long row = rowbase + lr;
        if (row < N_NODES) {
            int start = g_off[row];
            int deg = g_cnt[row];
            float dinv = g_dinv[row];

            // self-loop term: h[row] * dinv[row]
            float2 hv = __half22float2(g_hh[row * 32 + l]);
            float2 a = make_float2(hv.x * dinv, hv.y * dinv);

            int e = start, end = start + deg;
            for (; e + 3 < end; e += 4) {
                int s0 = g_srcs[e],     s1 = g_srcs[e + 1];
                int s2 = g_srcs[e + 2], s3 = g_srcs[e + 3];
                float d0 = g_dinv[s0], d1 = g_dinv[s1];
                float d2 = g_dinv[s2], d3 = g_dinv[s3];
                float2 v0 = __half22float2(g_hh[(long long)s0 * 32 + l]);
                float2 v1 = __half22float2(g_hh[(long long)s1 * 32 + l]);
                float2 v2 = __half22float2(g_hh[(long long)s2 * 32 + l]);
                float2 v3 = __half22float2(g_hh[(long long)s3 * 32 + l]);
                a.x += v0.x * d0 + v1.x * d1 + v2.x * d2 + v3.x * d3;
                a.y += v0.y * d0 + v1.y * d1 + v2.y * d2 + v3.y * d3;
            }
            for (; e < end; e++) {
                int s = g_srcs[e];
                float ds = g_dinv[s];
                float2 v = __half22float2(g_hh[(long long)s * 32 + l]);
                a.x += v.x * ds;
                a.y += v.y * ds;
            }

            float v0 = a.x * dinv + sb[2 * l];
            float v1 = a.y * dinv + sb[2 * l + 1];

            float s = v0 + v1;
            float q = v0 * v0 + v1 * v1;
#pragma unroll
            for (int o = 16; o; o >>= 1) {
                s += __shfl_xor_sync(0xFFFFFFFFu, s, o);
                q += __shfl_xor_sync(0xFFFFFFFFu, q, o);
            }
            float mu = s * (1.0f / 64.0f);
            float var = q * (1.0f / 64.0f) - mu * mu;
            float inv = rsqrtf(var + 1e-5f);

            float2 xv = *(const float2*)&x[row * 64 + 2 * l];
            rs[lr][2 * l]     = fmaxf((v0 - mu) * inv * sg[2 * l]     + sbe[2 * l],     0.f) * xv.x;
            rs[lr][2 * l + 1] = fmaxf((v1 - mu) * inv * sg[2 * l + 1] + sbe[2 * l + 1], 0.f) * xv.y;
        } else {
            rs[lr][2 * l] = 0.f;
            rs[lr][2 * l + 1] = 0.f;
        }
    }
    __syncthreads();

    // restore g_cnt == 0 for the next run (this block's 64 rows; all reads
    // of these entries happened in phase 1 above, fenced by __syncthreads)
    if (tid < 64) {
        long long row = rowbase + tid;
        if (row < N_NODES) g_cnt[row] = 0;
    }

    // ---- GEMM2: out = rs @ fcW + fcb (register-tiled 4x4, f32x2) ----
    int tx = tid & 15;
    int ty = tid >> 4;
    int r0 = ty * 4;
    int c0 = tx * 4;

    unsigned long long a01[4], a23[4];
#pragma unroll
    for (int i = 0; i < 4; i++) { a01[i] = 0ull; a23[i] = 0ull; }

#pragma unroll
    for (int k0 = 0; k0 < 64; k0 += 4) {
        float4 xv[4];
#pragma unroll
        for (int i = 0; i < 4; i++) xv[i] = *(float4*)&rs[r0 + i][k0];
#pragma unroll
        for (int kk = 0; kk < 4; kk++) {
            float4 wv = *(float4*)&Ws[(k0 + kk) * 64 + c0];
            unsigned long long w01 = pack2(wv.x, wv.y);
            unsigned long long w23 = pack2(wv.z, wv.w);
#pragma unroll
            for (int i = 0; i < 4; i++) {
                float xk = (kk == 0) ? xv[i].x : (kk == 1) ? xv[i].y
                         : (kk == 2) ? xv[i].z : xv[i].w;
                unsigned long long xx = pack2(xk, xk);
                a01[i] = ffma2(xx, w01, a01[i]);
                a23[i] = ffma2(xx, w23, a23[i]);
            }
        }
    }

#pragma unroll
    for (int i = 0; i < 4; i++) {
        long long row = rowbase + r0 + i;
        if (row < N_NODES) {
            float b0, b1, b2, b3;
            unpack2(a01[i], b0, b1);
            unpack2(a23[i], b2, b3);
            *(float4*)&out[row * 64 + c0] =
                make_float4(b0 + sfcb[c0], b1 + sfcb[c0 + 1],
                            b2 + sfcb[c0 + 2], b3 + sfcb[c0 + 3]);
        }
    }
}

// ---------------------------------------------------------------------------
extern "C" void kernel_launch(void* const* d_in, const int* in_sizes, int n_in,
                              void* d_out, int out_size) {
    const float* x     = (const float*)d_in[0];
    const int*   ei    = (const int*)d_in[1];   // int32 per harness metadata
    const float* W     = (const float*)d_in[2];
    const float* b     = (const float*)d_in[3];
    const float* gamma = (const float*)d_in[4];
    const float* beta  = (const float*)d_in[5];
    const float* fcW   = (const float*)d_in[6];
    const float* fcb   = (const float*)d_in[7];
    float* out = (float*)d_out;

    (void)in_sizes; (void)n_in; (void)out_size;

    k_count_gemm<<<G1_TILES + COUNT_BLOCKS, 256>>>(x, W, ei);
    k_scan1<<<NB_SCAN, 256>>>();
    k_scan23<<<NB_SCAN, 256>>>();
    k_fill<<<COUNT_BLOCKS, 256>>>(ei);
    k_gather_epi<<<EPI_TILES, 256>>>(x, b, gamma, beta, fcW, fcb, out);
}